// round 9
// baseline (speedup 1.0000x reference)
#include <cuda_runtime.h>
#include <cstdint>
#include <cstddef>

#define Bc 16
#define Nc 4096
#define Cc 512
#define Mc 32
#define ITERS 50
#define MU_ (1.0f/4096.0f)
#define OUT0 ((size_t)Bc*Nc*Cc)

typedef unsigned long long u64t;

// ---------------- device scratch (statics: the sanctioned no-alloc scratch) ----------------
static __device__ float g_yn[Bc*Mc*Cc];            // normalized target rows
static __device__ float g_Yt[Bc*Mc*Cc];            // target @ W_bot
static __device__ float g_cost[(size_t)Bc*Nc*Mc];  // 1 - cosine
static __device__ float g_K[(size_t)Bc*Nc*Mc];     // exp(-cost/0.05)
static __device__ float g_nu[Bc*Mc];
static __device__ int   g_counts[Bc*Mc];
static __device__ float g_vhist[Bc*ITERS*Mc];
static __device__ float g_errhist[Bc*ITERS];
static __device__ float g_vfin[Bc*Mc];
static __device__ float g_vprev[Bc*Mc];
static __device__ float g_pn[(size_t)Bc*Nc*Mc];    // pi_norm
static __device__ float g_otPart[Bc*8];
static __device__ float g_H[(size_t)Bc*Nc*Cc];     // pre-LN activations

__device__ __forceinline__ float wsum(float v) {
    v += __shfl_xor_sync(0xffffffffu, v, 16);
    v += __shfl_xor_sync(0xffffffffu, v, 8);
    v += __shfl_xor_sync(0xffffffffu, v, 4);
    v += __shfl_xor_sync(0xffffffffu, v, 2);
    v += __shfl_xor_sync(0xffffffffu, v, 1);
    return v;
}

// ---- packed f32x2 helpers (FFMA2 path: doubled fp32 FMA throughput) ----
__device__ __forceinline__ u64t pack2(float lo, float hi) {
    u64t r; asm("mov.b64 %0, {%1, %2};" : "=l"(r) : "f"(lo), "f"(hi)); return r;
}
__device__ __forceinline__ void unpack2(u64t v, float& lo, float& hi) {
    asm("mov.b64 {%0, %1}, %2;" : "=f"(lo), "=f"(hi) : "l"(v));
}
__device__ __forceinline__ u64t fma2(u64t a, u64t b, u64t c) {
    u64t d; asm("fma.rn.f32x2 %0, %1, %2, %3;" : "=l"(d) : "l"(a), "l"(b), "l"(c));
    return d;
}

// ---------------- reset persistent accumulators (re-run every replay) ----------------
__global__ void reset_kernel() {
    int tid = threadIdx.x;
    if (tid < Bc*Mc) g_counts[tid] = 0;
}

// ---------------- nu: argmax histogram over score_map [B,K,H,W] ----------------
__global__ void hist_kernel(const float* __restrict__ score) {
    __shared__ int h[Mc];
    int b = blockIdx.x >> 4, chunk = blockIdx.x & 15;
    int tid = threadIdx.x;
    if (tid < Mc) h[tid] = 0;
    __syncthreads();
    int p = chunk*256 + tid;
    const float* s = score + (size_t)b*Mc*Nc + p;
    float best = s[0]; int bi = 0;
#pragma unroll
    for (int k = 1; k < Mc; k++) {
        float v = s[(size_t)k*Nc];
        if (v > best) { best = v; bi = k; }
    }
    atomicAdd(&h[bi], 1);
    __syncthreads();
    if (tid < Mc) atomicAdd(&g_counts[b*Mc + tid], h[tid]);
}

__global__ void nu_kernel() {
    int tid = threadIdx.x;                 // 512 threads: warp = batch
    int b = tid >> 5, m = tid & 31;
    float c = (float)g_counts[b*Mc + m];
    float total = wsum(c);
    float nu1 = c / (total + 1e-8f);
    float nu2 = nu1 + 1e-6f;
    float s2 = wsum(nu2);
    g_nu[b*Mc + m] = nu2 / s2;
}

// ---------------- target row-normalize ----------------
__global__ void yn_kernel(const float* __restrict__ tgt) {
    int b = blockIdx.x;
    int w = threadIdx.x >> 5, lane = threadIdx.x & 31;   // 16 warps
    for (int m = w; m < Mc; m += 16) {
        const float* y = tgt + ((size_t)(b*Mc + m))*Cc;
        float ss = 0.f;
        for (int j = lane*4; j < Cc; j += 128) {
            float4 v = *(const float4*)(y + j);
            ss += v.x*v.x + v.y*v.y + v.z*v.z + v.w*v.w;
        }
        ss = wsum(ss);
        float inv = rsqrtf(ss);
        for (int j = lane*4; j < Cc; j += 128) {
            float4 v = *(const float4*)(y + j);
            float4 o; o.x = v.x*inv; o.y = v.y*inv; o.z = v.z*inv; o.w = v.w*inv;
            *(float4*)(g_yn + ((size_t)(b*Mc + m))*Cc + j) = o;
        }
    }
}

// ---------------- Yt = target @ W_bot  (W rows 512..1023) ----------------
__global__ void __launch_bounds__(128) yt_kernel(const float* __restrict__ tgt,
                                                 const float* __restrict__ W) {
    int b  = blockIdx.x >> 2;
    int c0 = (blockIdx.x & 3) * 128;
    int c  = c0 + threadIdx.x;
    __shared__ float st[64][33];     // [kk][m]
    float acc[Mc];
#pragma unroll
    for (int m = 0; m < Mc; m++) acc[m] = 0.f;
    for (int k0 = 0; k0 < Cc; k0 += 64) {
        __syncthreads();
        for (int i = threadIdx.x; i < 512; i += 128) {   // 32 m x 16 float4
            int m = i >> 4, kq = i & 15;
            float4 v = *(const float4*)(tgt + ((size_t)(b*Mc + m))*Cc + k0 + kq*4);
            st[kq*4+0][m] = v.x; st[kq*4+1][m] = v.y;
            st[kq*4+2][m] = v.z; st[kq*4+3][m] = v.w;
        }
        __syncthreads();
        for (int kk = 0; kk < 64; kk++) {
            float w = W[(size_t)(Cc + k0 + kk)*Cc + c];
#pragma unroll
            for (int m = 0; m < Mc; m++) acc[m] = fmaf(st[kk][m], w, acc[m]);
        }
    }
#pragma unroll
    for (int m = 0; m < Mc; m++)
        g_Yt[((size_t)(b*Mc + m))*Cc + c] = acc[m];
}

// ---------------- cost & K: per (b, 128-row tile), packed f32x2 ----------------
__global__ void __launch_bounds__(256) cost_kernel(const float* __restrict__ src) {
    __shared__ float As[32][132];
    __shared__ float Bs[32][36];
    int b  = blockIdx.x >> 5;
    int r0 = (blockIdx.x & 31) * 128;
    int tid = threadIdx.x;
    int tx = tid & 7, ty = tid >> 3;           // tx: 8 m-groups(4), ty: 32 row-groups(4)
    u64t acc2[4][2];                           // [i][h] = (acc[i][2h], acc[i][2h+1])
    u64t accn2[2];                             // (n0,n1),(n2,n3)
#pragma unroll
    for (int i = 0; i < 4; i++) { acc2[i][0] = 0ull; acc2[i][1] = 0ull; }
    accn2[0] = 0ull; accn2[1] = 0ull;
    for (int k0 = 0; k0 < Cc; k0 += 32) {
        __syncthreads();
        for (int i = tid; i < 1024; i += 256) {          // 128 rows x 8 float4
            int r = i >> 3, kq = i & 7;
            float4 v = *(const float4*)(src + ((size_t)(b*Nc + r0 + r))*Cc + k0 + kq*4);
            As[kq*4+0][r] = v.x; As[kq*4+1][r] = v.y;
            As[kq*4+2][r] = v.z; As[kq*4+3][r] = v.w;
        }
        {
            int i = tid;
            if (i < 256) {                               // 32 m x 8 float4
                int m = i >> 3, kq = i & 7;
                float4 v = *(const float4*)(g_yn + ((size_t)(b*Mc + m))*Cc + k0 + kq*4);
                Bs[kq*4+0][m] = v.x; Bs[kq*4+1][m] = v.y;
                Bs[kq*4+2][m] = v.z; Bs[kq*4+3][m] = v.w;
            }
        }
        __syncthreads();
#pragma unroll
        for (int k = 0; k < 32; k++) {
            float4 av = *(const float4*)&As[k][ty*4];
            float4 bv = *(const float4*)&Bs[k][tx*4];
            u64t an0 = pack2(av.x, av.y), an1 = pack2(av.z, av.w);
            u64t bp0 = pack2(bv.x, bv.y), bp1 = pack2(bv.z, bv.w);
            accn2[0] = fma2(an0, an0, accn2[0]);
            accn2[1] = fma2(an1, an1, accn2[1]);
            u64t ad0 = pack2(av.x, av.x), ad1 = pack2(av.y, av.y);
            u64t ad2 = pack2(av.z, av.z), ad3 = pack2(av.w, av.w);
            acc2[0][0] = fma2(ad0, bp0, acc2[0][0]); acc2[0][1] = fma2(ad0, bp1, acc2[0][1]);
            acc2[1][0] = fma2(ad1, bp0, acc2[1][0]); acc2[1][1] = fma2(ad1, bp1, acc2[1][1]);
            acc2[2][0] = fma2(ad2, bp0, acc2[2][0]); acc2[2][1] = fma2(ad2, bp1, acc2[2][1]);
            acc2[3][0] = fma2(ad3, bp0, acc2[3][0]); acc2[3][1] = fma2(ad3, bp1, acc2[3][1]);
        }
    }
    float accn[4], acc[4][4];
    unpack2(accn2[0], accn[0], accn[1]);
    unpack2(accn2[1], accn[2], accn[3]);
#pragma unroll
    for (int i = 0; i < 4; i++) {
        unpack2(acc2[i][0], acc[i][0], acc[i][1]);
        unpack2(acc2[i][1], acc[i][2], acc[i][3]);
    }
#pragma unroll
    for (int i = 0; i < 4; i++) {
        int n = r0 + ty*4 + i;
        float inv = rsqrtf(accn[i]);
        float4 cv, kv;
        cv.x = 1.f - acc[i][0]*inv; cv.y = 1.f - acc[i][1]*inv;
        cv.z = 1.f - acc[i][2]*inv; cv.w = 1.f - acc[i][3]*inv;
        kv.x = expf(-cv.x/0.05f); kv.y = expf(-cv.y/0.05f);
        kv.z = expf(-cv.z/0.05f); kv.w = expf(-cv.w/0.05f);
        size_t base = ((size_t)(b*Nc + n))*Mc + tx*4;
        *(float4*)(g_cost + base) = cv;
        *(float4*)(g_K + base)    = kv;
    }
}

// ---------------- Sinkhorn: one CTA per batch, 512 threads, packed f32x2 ----------------
__global__ void __launch_bounds__(512, 1) sinkhorn_kernel() {
    int b   = blockIdx.x;
    int tid = threadIdx.x;
    int lane = tid & 31, wid = tid >> 5;
    __shared__ float sv[Mc];
    __shared__ float snu[Mc];
    __shared__ float sS[16][33];
    __shared__ float sErr[16];
    if (tid < Mc) { sv[tid] = 0.f; snu[tid] = g_nu[b*Mc + tid]; }
    __syncthreads();
    float u[8];
#pragma unroll
    for (int j = 0; j < 8; j++) u[j] = 0.f;
    const float* Kb = g_K + (size_t)b*Nc*Mc;
    for (int t = 0; t < ITERS; t++) {
        u64t vr2[16];
#pragma unroll
        for (int q = 0; q < 16; q++) vr2[q] = pack2(sv[2*q], sv[2*q+1]);
        u64t S2[16];
#pragma unroll
        for (int q = 0; q < 16; q++) S2[q] = 0ull;
        float errLoc = 0.f;
#pragma unroll
        for (int j = 0; j < 8; j++) {
            int n = j*512 + tid;
            const ulonglong2* kp = (const ulonglong2*)(Kb + (size_t)n*Mc);
            u64t k2[16];
#pragma unroll
            for (int q = 0; q < 8; q++) {
                ulonglong2 v = kp[q];
                k2[2*q] = v.x; k2[2*q+1] = v.y;
            }
            u64t d2 = 0ull;
#pragma unroll
            for (int q = 0; q < 16; q++) d2 = fma2(k2[q], vr2[q], d2);
            float dl, dh; unpack2(d2, dl, dh);
            float un = MU_ / ((dl + dh) + 1e-8f);
            errLoc += fabsf(un - u[j]);
            u[j] = un;
            u64t u2 = pack2(un, un);
#pragma unroll
            for (int q = 0; q < 16; q++) S2[q] = fma2(k2[q], u2, S2[q]);
        }
        float S[Mc];
#pragma unroll
        for (int q = 0; q < 16; q++) unpack2(S2[q], S[2*q], S[2*q+1]);
#pragma unroll
        for (int m = 0; m < Mc; m++) S[m] = wsum(S[m]);
        errLoc = wsum(errLoc);
        if (lane == 0) {
#pragma unroll
            for (int m = 0; m < Mc; m++) sS[wid][m] = S[m];
            sErr[wid] = errLoc;
        }
        __syncthreads();
        if (tid < Mc) {
            float s = 0.f;
#pragma unroll
            for (int w = 0; w < 16; w++) s += sS[w][tid];
            float vnew = snu[tid] / (s + 1e-8f);
            sv[tid] = vnew;
            g_vhist[((size_t)b*ITERS + t)*Mc + tid] = vnew;
        }
        if (tid == 32) {
            float e = 0.f;
            for (int w = 0; w < 16; w++) e += sErr[w];
            g_errhist[b*ITERS + t] = e;
        }
        __syncthreads();
    }
}

// ---------------- pick iteration T (global early-stop), extract v_T, v_{T-1} ----------------
__global__ void pick_kernel() {
    __shared__ int sT;
    if (threadIdx.x == 0) {
        int T = ITERS - 1;
        for (int t = 0; t < ITERS; t++) {
            float e = 0.f;
            for (int b = 0; b < Bc; b++) e += g_errhist[b*ITERS + t];
            e *= (1.0f/(float)Bc);
            if (e < 0.1f) { T = t; break; }
        }
        sT = T;
    }
    __syncthreads();
    int T = sT;
    int m = threadIdx.x;
    if (m < Mc) {
        for (int b = 0; b < Bc; b++) {
            g_vfin[b*Mc + m]  = g_vhist[((size_t)b*ITERS + T)*Mc + m];
            g_vprev[b*Mc + m] = (T > 0) ? g_vhist[((size_t)b*ITERS + T - 1)*Mc + m] : 0.f;
        }
    }
}

// ---------------- finalize: u_T, pi, ot partials, pi_norm ----------------
__global__ void __launch_bounds__(256) finalize_kernel(float* __restrict__ out) {
    int b  = blockIdx.x >> 3;
    int r0 = (blockIdx.x & 7) * 512;
    __shared__ float svp[Mc], svf[Mc];
    __shared__ float red[256];
    int tid = threadIdx.x;
    if (tid < Mc) { svp[tid] = g_vprev[b*Mc + tid]; svf[tid] = g_vfin[b*Mc + tid]; }
    __syncthreads();
    float vp[Mc], vf[Mc];
#pragma unroll
    for (int m = 0; m < Mc; m++) { vp[m] = svp[m]; vf[m] = svf[m]; }
    float otLoc = 0.f;
    for (int jj = 0; jj < 2; jj++) {
        int n = r0 + jj*256 + tid;
        size_t base = ((size_t)(b*Nc + n))*Mc;
        const float4* kp = (const float4*)(g_K + base);
        const float4* cp = (const float4*)(g_cost + base);
        float kr[Mc];
#pragma unroll
        for (int q = 0; q < 8; q++) {
            float4 v = kp[q];
            kr[q*4+0] = v.x; kr[q*4+1] = v.y; kr[q*4+2] = v.z; kr[q*4+3] = v.w;
        }
        float d = 0.f;
#pragma unroll
        for (int m = 0; m < Mc; m++) d = fmaf(kr[m], vp[m], d);
        float u = MU_ / (d + 1e-8f);
        float pi[Mc]; float s = 0.f;
#pragma unroll
        for (int m = 0; m < Mc; m++) { pi[m] = u * kr[m] * vf[m]; s += pi[m]; }
#pragma unroll
        for (int q = 0; q < 8; q++) {
            float4 c4 = cp[q];
            otLoc += pi[q*4+0]*c4.x + pi[q*4+1]*c4.y + pi[q*4+2]*c4.z + pi[q*4+3]*c4.w;
        }
        float inv = 1.f/(s + 1e-8f);
        float* piOut = out + OUT0 + Bc + base;
#pragma unroll
        for (int q = 0; q < 8; q++) {
            float4 o;  o.x = pi[q*4+0]; o.y = pi[q*4+1]; o.z = pi[q*4+2]; o.w = pi[q*4+3];
            *(float4*)(piOut + q*4) = o;
            float4 pn; pn.x = o.x*inv; pn.y = o.y*inv; pn.z = o.z*inv; pn.w = o.w*inv;
            *(float4*)(g_pn + base + q*4) = pn;
        }
    }
    red[tid] = otLoc;
    __syncthreads();
    for (int s2 = 128; s2 > 0; s2 >>= 1) {
        if (tid < s2) red[tid] += red[tid + s2];
        __syncthreads();
    }
    if (tid == 0) g_otPart[blockIdx.x] = red[0];
}

__global__ void otsum_kernel(float* __restrict__ out) {
    int b = threadIdx.x;
    if (b < Bc) {
        float s = 0.f;
        for (int i = 0; i < 8; i++) s += g_otPart[b*8 + i];
        out[OUT0 + b] = s;
    }
}

// ---------------- H = [src | pn] @ [W_top ; Yt_b] + bias : packed-f32x2 GEMM ----------------
// A tile stored DUPLICATED in smem: As2[k][2r]=As2[k][2r+1]=A[row][k], so a
// 64-bit smem load yields a ready (a,a) f32x2 pair with zero pack instructions.
__device__ __forceinline__ void storeA_dup(float (*As2)[264], int idx, float4 v) {
    int r = idx >> 2, kq = idx & 3;
    float2 d;
    d.x = v.x; d.y = v.x; *(float2*)&As2[kq*4+0][2*r] = d;
    d.x = v.y; d.y = v.y; *(float2*)&As2[kq*4+1][2*r] = d;
    d.x = v.z; d.y = v.z; *(float2*)&As2[kq*4+2][2*r] = d;
    d.x = v.w; d.y = v.w; *(float2*)&As2[kq*4+3][2*r] = d;
}

__global__ void __launch_bounds__(256) gemm_kernel(const float* __restrict__ src,
                                                   const float* __restrict__ W,
                                                   const float* __restrict__ bias) {
    __shared__ float As2[16][264];   // duplicated pairs
    __shared__ float Bs[16][128];
    int row0 = blockIdx.x * 128;
    int c0   = blockIdx.y * 128;
    int b    = row0 >> 12;
    int tid  = threadIdx.x;
    int tx = tid & 15, ty = tid >> 4;

    u64t acc2[8][4];
#pragma unroll
    for (int i = 0; i < 8; i++)
#pragma unroll
        for (int j = 0; j < 4; j++) acc2[i][j] = 0ull;

    float4 ra[2], rb[2];
    // prologue: k-tile 0 (always src/W region)
#pragma unroll
    for (int q = 0; q < 2; q++) {
        int idx = tid*2 + q; int r = idx >> 2, kq = idx & 3;
        ra[q] = *(const float4*)(src + ((size_t)(row0 + r))*Cc + kq*4);
        int kr = idx >> 5, cq = idx & 31;
        rb[q] = *(const float4*)(W + ((size_t)kr)*Cc + c0 + cq*4);
    }
#pragma unroll
    for (int q = 0; q < 2; q++) {
        int idx = tid*2 + q;
        storeA_dup(As2, idx, ra[q]);
        int kr = idx >> 5, cq = idx & 31;
        *(float4*)&Bs[kr][cq*4] = rb[q];
    }
    __syncthreads();

    for (int kt = 0; kt < 34; kt++) {
        int k0n = (kt + 1) * 16;
        if (kt + 1 < 34) {
#pragma unroll
            for (int q = 0; q < 2; q++) {
                int idx = tid*2 + q; int r = idx >> 2, kq = idx & 3;
                if (k0n < 512)
                    ra[q] = *(const float4*)(src + ((size_t)(row0 + r))*Cc + k0n + kq*4);
                else
                    ra[q] = *(const float4*)(g_pn + ((size_t)(row0 + r))*Mc + (k0n - 512) + kq*4);
                int kr = idx >> 5, cq = idx & 31;
                if (k0n < 512)
                    rb[q] = *(const float4*)(W + ((size_t)(k0n + kr))*Cc + c0 + cq*4);
                else
                    rb[q] = *(const float4*)(g_Yt + ((size_t)(b*Mc + (k0n - 512) + kr))*Cc + c0 + cq*4);
            }
        }
#pragma unroll
        for (int k = 0; k < 16; k++) {
            u64t a2[8], b2[4];
            const ulonglong2* ap = (const ulonglong2*)&As2[k][ty*16];
#pragma unroll
            for (int q = 0; q < 4; q++) { ulonglong2 t2 = ap[q]; a2[2*q] = t2.x; a2[2*q+1] = t2.y; }
            const ulonglong2* bp = (const ulonglong2*)&Bs[k][tx*8];
#pragma unroll
            for (int q = 0; q < 2; q++) { ulonglong2 t2 = bp[q]; b2[2*q] = t2.x; b2[2*q+1] = t2.y; }
#pragma unroll
            for (int i = 0; i < 8; i++)
#pragma unroll
                for (int j = 0; j < 4; j++)
                    acc2[i][j] = fma2(a2[i], b2[j], acc2[i][j]);
        }
        __syncthreads();
        if (kt + 1 < 34) {
#pragma unroll
            for (int q = 0; q < 2; q++) {
                int idx = tid*2 + q;
                storeA_dup(As2, idx, ra[q]);
                int kr = idx >> 5, cq = idx & 31;
                *(float4*)&Bs[kr][cq*4] = rb[q];
            }
            __syncthreads();
        }
    }

#pragma unroll
    for (int i = 0; i < 8; i++) {
        float f[8];
#pragma unroll
        for (int j = 0; j < 4; j++) unpack2(acc2[i][j], f[2*j], f[2*j+1]);
        size_t g = (size_t)(row0 + ty*8 + i)*Cc + c0 + tx*8;
#pragma unroll
        for (int j4 = 0; j4 < 2; j4++) {
            float4 bv = *(const float4*)(bias + c0 + tx*8 + j4*4);
            float4 o;
            o.x = f[j4*4+0] + bv.x; o.y = f[j4*4+1] + bv.y;
            o.z = f[j4*4+2] + bv.z; o.w = f[j4*4+3] + bv.w;
            *(float4*)(g_H + g + j4*4) = o;
        }
    }
}

// ---------------- LayerNorm over C=512, one warp per row ----------------
__global__ void __launch_bounds__(256) ln_kernel(float* __restrict__ out,
                                                 const float* __restrict__ gamma,
                                                 const float* __restrict__ beta) {
    int row  = blockIdx.x*8 + (threadIdx.x >> 5);
    int lane = threadIdx.x & 31;
    const float* h = g_H + (size_t)row*Cc;
    float4 x[4];
    float s = 0.f;
#pragma unroll
    for (int q = 0; q < 4; q++) {
        x[q] = *(const float4*)(h + q*128 + lane*4);
        s += x[q].x + x[q].y + x[q].z + x[q].w;
    }
    s = wsum(s);
    float mean = s * (1.0f/512.0f);
    float var = 0.f;
#pragma unroll
    for (int q = 0; q < 4; q++) {
        float a = x[q].x - mean, b2 = x[q].y - mean, c = x[q].z - mean, d = x[q].w - mean;
        var += a*a + b2*b2 + c*c + d*d;
    }
    var = wsum(var) * (1.0f/512.0f);
    float inv = rsqrtf(var + 1e-5f);
    float* o = out + (size_t)row*Cc;
#pragma unroll
    for (int q = 0; q < 4; q++) {
        int c = q*128 + lane*4;
        float4 g4 = *(const float4*)(gamma + c);
        float4 b4 = *(const float4*)(beta + c);
        float4 r;
        r.x = (x[q].x - mean)*inv*g4.x + b4.x;
        r.y = (x[q].y - mean)*inv*g4.y + b4.y;
        r.z = (x[q].z - mean)*inv*g4.z + b4.z;
        r.w = (x[q].w - mean)*inv*g4.w + b4.w;
        *(float4*)(o + c) = r;
    }
}

// ---------------- launcher ----------------
extern "C" void kernel_launch(void* const* d_in, const int* in_sizes, int n_in,
                              void* d_out, int out_size) {
    const float* src   = (const float*)d_in[0];   // [B, N, C]
    const float* tgt   = (const float*)d_in[1];   // [B, M, C]
    const float* score = (const float*)d_in[2];   // [B, M, H, W]
    const float* W     = (const float*)d_in[3];   // [2C, C]
    const float* bias  = (const float*)d_in[4];   // [C]
    const float* gamma = (const float*)d_in[5];   // [C]
    const float* beta  = (const float*)d_in[6];   // [C]
    float* out = (float*)d_out;                   // [B*N*C | B | B*N*M]

    reset_kernel<<<1, 512>>>();
    hist_kernel<<<Bc*16, 256>>>(score);
    nu_kernel<<<1, 512>>>();
    yn_kernel<<<Bc, 512>>>(tgt);
    yt_kernel<<<Bc*4, 128>>>(tgt, W);
    cost_kernel<<<Bc*32, 256>>>(src);
    sinkhorn_kernel<<<Bc, 512>>>();
    pick_kernel<<<1, 32>>>();
    finalize_kernel<<<Bc*8, 256>>>(out);
    otsum_kernel<<<1, 32>>>(out);
    gemm_kernel<<<dim3(512, 4), 256>>>(src, W, bias);
    ln_kernel<<<8192, 256>>>(out, gamma, beta);
}

// round 10
// speedup vs baseline: 1.2574x; 1.2574x over previous
#include <cuda_runtime.h>
#include <cuda_bf16.h>
#include <cstdint>
#include <cstddef>

#define Bc 16
#define Nc 4096
#define Cc 512
#define Mc 32
#define ITERS 50
#define MU_ (1.0f/4096.0f)
#define OUT0 ((size_t)Bc*Nc*Cc)
#define KK 544                 // 512 + 32 fused-K
#define ROWS ((size_t)Bc*Nc)   // 65536

// ---------------- device scratch (statics: the sanctioned no-alloc scratch) ----------------
static __device__ float g_yn[Bc*Mc*Cc];
static __device__ float g_Yt[Bc*Mc*Cc];
static __device__ float g_cost[(size_t)Bc*Nc*Mc];
static __device__ float g_K[(size_t)Bc*Nc*Mc];
static __device__ float g_nu[Bc*Mc];
static __device__ int   g_counts[Bc*Mc];
static __device__ float g_vhist[Bc*ITERS*Mc];
static __device__ float g_errhist[Bc*ITERS];
static __device__ float g_vfin[Bc*Mc];
static __device__ float g_vprev[Bc*Mc];
static __device__ float g_pn[(size_t)Bc*Nc*Mc];
static __device__ float g_otPart[Bc*8];
static __device__ float g_H[(size_t)Bc*Nc*Cc];
// bf16 split operands for the tensor-core GEMM
static __device__ __nv_bfloat16 g_Ah[ROWS*KK];
static __device__ __nv_bfloat16 g_Al[ROWS*KK];
static __device__ __nv_bfloat16 g_Bth[(size_t)Bc*Cc*KK];   // B' transposed: [b][c][k]
static __device__ __nv_bfloat16 g_Btl[(size_t)Bc*Cc*KK];

__device__ __forceinline__ float wsum(float v) {
    v += __shfl_xor_sync(0xffffffffu, v, 16);
    v += __shfl_xor_sync(0xffffffffu, v, 8);
    v += __shfl_xor_sync(0xffffffffu, v, 4);
    v += __shfl_xor_sync(0xffffffffu, v, 2);
    v += __shfl_xor_sync(0xffffffffu, v, 1);
    return v;
}

__device__ __forceinline__ void split_bf16(float x, __nv_bfloat16& h, __nv_bfloat16& l) {
    h = __float2bfloat16(x);
    l = __float2bfloat16(x - __bfloat162float(h));
}

__device__ __forceinline__ void ldsm_x4(unsigned* r, uint32_t addr) {
    asm volatile("ldmatrix.sync.aligned.m8n8.x4.shared.b16 {%0,%1,%2,%3}, [%4];\n"
        : "=r"(r[0]), "=r"(r[1]), "=r"(r[2]), "=r"(r[3]) : "r"(addr));
}

__device__ __forceinline__ void mma_bf16(float* d, const unsigned* a, const unsigned* b) {
    asm volatile("mma.sync.aligned.m16n8k16.row.col.f32.bf16.bf16.f32 "
        "{%0,%1,%2,%3}, {%4,%5,%6,%7}, {%8,%9}, {%0,%1,%2,%3};\n"
        : "+f"(d[0]), "+f"(d[1]), "+f"(d[2]), "+f"(d[3])
        : "r"(a[0]), "r"(a[1]), "r"(a[2]), "r"(a[3]), "r"(b[0]), "r"(b[1]));
}

// ---------------- reset ----------------
__global__ void reset_kernel() {
    int tid = threadIdx.x;
    if (tid < Bc*Mc) g_counts[tid] = 0;
}

// ---------------- nu histogram ----------------
__global__ void hist_kernel(const float* __restrict__ score) {
    __shared__ int h[Mc];
    int b = blockIdx.x >> 4, chunk = blockIdx.x & 15;
    int tid = threadIdx.x;
    if (tid < Mc) h[tid] = 0;
    __syncthreads();
    int p = chunk*256 + tid;
    const float* s = score + (size_t)b*Mc*Nc + p;
    float best = s[0]; int bi = 0;
#pragma unroll
    for (int k = 1; k < Mc; k++) {
        float v = s[(size_t)k*Nc];
        if (v > best) { best = v; bi = k; }
    }
    atomicAdd(&h[bi], 1);
    __syncthreads();
    if (tid < Mc) atomicAdd(&g_counts[b*Mc + tid], h[tid]);
}

__global__ void nu_kernel() {
    int tid = threadIdx.x;
    int b = tid >> 5, m = tid & 31;
    float c = (float)g_counts[b*Mc + m];
    float total = wsum(c);
    float nu1 = c / (total + 1e-8f);
    float nu2 = nu1 + 1e-6f;
    float s2 = wsum(nu2);
    g_nu[b*Mc + m] = nu2 / s2;
}

// ---------------- target row-normalize ----------------
__global__ void yn_kernel(const float* __restrict__ tgt) {
    int b = blockIdx.x;
    int w = threadIdx.x >> 5, lane = threadIdx.x & 31;
    for (int m = w; m < Mc; m += 16) {
        const float* y = tgt + ((size_t)(b*Mc + m))*Cc;
        float ss = 0.f;
        for (int j = lane*4; j < Cc; j += 128) {
            float4 v = *(const float4*)(y + j);
            ss += v.x*v.x + v.y*v.y + v.z*v.z + v.w*v.w;
        }
        ss = wsum(ss);
        float inv = rsqrtf(ss);
        for (int j = lane*4; j < Cc; j += 128) {
            float4 v = *(const float4*)(y + j);
            float4 o; o.x = v.x*inv; o.y = v.y*inv; o.z = v.z*inv; o.w = v.w*inv;
            *(float4*)(g_yn + ((size_t)(b*Mc + m))*Cc + j) = o;
        }
    }
}

// ---------------- Yt = target @ W_bot ----------------
__global__ void __launch_bounds__(128) yt_kernel(const float* __restrict__ tgt,
                                                 const float* __restrict__ W) {
    int b  = blockIdx.x >> 2;
    int c0 = (blockIdx.x & 3) * 128;
    int c  = c0 + threadIdx.x;
    __shared__ float st[64][33];
    float acc[Mc];
#pragma unroll
    for (int m = 0; m < Mc; m++) acc[m] = 0.f;
    for (int k0 = 0; k0 < Cc; k0 += 64) {
        __syncthreads();
        for (int i = threadIdx.x; i < 512; i += 128) {
            int m = i >> 4, kq = i & 15;
            float4 v = *(const float4*)(tgt + ((size_t)(b*Mc + m))*Cc + k0 + kq*4);
            st[kq*4+0][m] = v.x; st[kq*4+1][m] = v.y;
            st[kq*4+2][m] = v.z; st[kq*4+3][m] = v.w;
        }
        __syncthreads();
        for (int kk = 0; kk < 64; kk++) {
            float w = W[(size_t)(Cc + k0 + kk)*Cc + c];
#pragma unroll
            for (int m = 0; m < Mc; m++) acc[m] = fmaf(st[kk][m], w, acc[m]);
        }
    }
#pragma unroll
    for (int m = 0; m < Mc; m++)
        g_Yt[((size_t)(b*Mc + m))*Cc + c] = acc[m];
}

// ---------------- convB: build transposed split-bf16 B' = [W_top ; Yt_b], layout [b][c][k] ----------------
__global__ void convB_kernel(const float* __restrict__ W) {
    __shared__ float t[32][33];
    int kt = blockIdx.x;          // 0..16  (k tiles of 32)
    int ct = blockIdx.y;          // 0..15  (c tiles of 32)
    int b  = blockIdx.z;
    int tx = threadIdx.x, ty = threadIdx.y;      // 32 x 8
#pragma unroll
    for (int i = 0; i < 4; i++) {
        int k = kt*32 + ty + i*8;
        int c = ct*32 + tx;
        float v = (k < Cc) ? W[(size_t)k*Cc + c]
                           : g_Yt[((size_t)(b*Mc + (k - Cc)))*Cc + c];
        t[ty + i*8][tx] = v;
    }
    __syncthreads();
#pragma unroll
    for (int i = 0; i < 4; i++) {
        int c = ct*32 + ty + i*8;
        int k = kt*32 + tx;
        float v = t[tx][ty + i*8];
        __nv_bfloat16 h, l; split_bf16(v, h, l);
        size_t o = (size_t)b*Cc*KK + (size_t)c*KK + k;
        g_Bth[o] = h; g_Btl[o] = l;
    }
}

// ---------------- convA: split-bf16 of A' rows (src part, pn part) ----------------
__global__ void __launch_bounds__(256) convA_src_kernel(const float* __restrict__ src) {
    size_t gid = (size_t)blockIdx.x*256 + threadIdx.x;   // over ROWS*128
    size_t row = gid >> 7; int kq = (int)(gid & 127);
    float4 v = *(const float4*)(src + row*Cc + kq*4);
    __nv_bfloat16 h[4], l[4];
    split_bf16(v.x, h[0], l[0]); split_bf16(v.y, h[1], l[1]);
    split_bf16(v.z, h[2], l[2]); split_bf16(v.w, h[3], l[3]);
    size_t o = row*KK + kq*4;
    *(__nv_bfloat162*)(g_Ah + o)     = __nv_bfloat162{h[0], h[1]};
    *(__nv_bfloat162*)(g_Ah + o + 2) = __nv_bfloat162{h[2], h[3]};
    *(__nv_bfloat162*)(g_Al + o)     = __nv_bfloat162{l[0], l[1]};
    *(__nv_bfloat162*)(g_Al + o + 2) = __nv_bfloat162{l[2], l[3]};
}

__global__ void __launch_bounds__(256) convA_pn_kernel() {
    size_t gid = (size_t)blockIdx.x*256 + threadIdx.x;   // over ROWS*8
    size_t row = gid >> 3; int kq = (int)(gid & 7);
    float4 v = *(const float4*)(g_pn + row*Mc + kq*4);
    __nv_bfloat16 h[4], l[4];
    split_bf16(v.x, h[0], l[0]); split_bf16(v.y, h[1], l[1]);
    split_bf16(v.z, h[2], l[2]); split_bf16(v.w, h[3], l[3]);
    size_t o = row*KK + Cc + kq*4;
    *(__nv_bfloat162*)(g_Ah + o)     = __nv_bfloat162{h[0], h[1]};
    *(__nv_bfloat162*)(g_Ah + o + 2) = __nv_bfloat162{h[2], h[3]};
    *(__nv_bfloat162*)(g_Al + o)     = __nv_bfloat162{l[0], l[1]};
    *(__nv_bfloat162*)(g_Al + o + 2) = __nv_bfloat162{l[2], l[3]};
}

// ---------------- cost & K (plain fp32 — R8 baseline) ----------------
__global__ void __launch_bounds__(256) cost_kernel(const float* __restrict__ src) {
    __shared__ float As[32][132];
    __shared__ float Bs[32][36];
    int b  = blockIdx.x >> 5;
    int r0 = (blockIdx.x & 31) * 128;
    int tid = threadIdx.x;
    int tx = tid & 7, ty = tid >> 3;
    float acc[4][4], accn[4];
#pragma unroll
    for (int i = 0; i < 4; i++) {
        accn[i] = 0.f;
#pragma unroll
        for (int j = 0; j < 4; j++) acc[i][j] = 0.f;
    }
    for (int k0 = 0; k0 < Cc; k0 += 32) {
        __syncthreads();
        for (int i = tid; i < 1024; i += 256) {
            int r = i >> 3, kq = i & 7;
            float4 v = *(const float4*)(src + ((size_t)(b*Nc + r0 + r))*Cc + k0 + kq*4);
            As[kq*4+0][r] = v.x; As[kq*4+1][r] = v.y;
            As[kq*4+2][r] = v.z; As[kq*4+3][r] = v.w;
        }
        if (tid < 256) {
            int m = tid >> 3, kq = tid & 7;
            float4 v = *(const float4*)(g_yn + ((size_t)(b*Mc + m))*Cc + k0 + kq*4);
            Bs[kq*4+0][m] = v.x; Bs[kq*4+1][m] = v.y;
            Bs[kq*4+2][m] = v.z; Bs[kq*4+3][m] = v.w;
        }
        __syncthreads();
#pragma unroll
        for (int k = 0; k < 32; k++) {
            float a[4], bb[4];
#pragma unroll
            for (int i = 0; i < 4; i++) a[i] = As[k][ty*4 + i];
#pragma unroll
            for (int j = 0; j < 4; j++) bb[j] = Bs[k][tx*4 + j];
#pragma unroll
            for (int i = 0; i < 4; i++) {
                accn[i] = fmaf(a[i], a[i], accn[i]);
#pragma unroll
                for (int j = 0; j < 4; j++) acc[i][j] = fmaf(a[i], bb[j], acc[i][j]);
            }
        }
    }
#pragma unroll
    for (int i = 0; i < 4; i++) {
        int n = r0 + ty*4 + i;
        float inv = rsqrtf(accn[i]);
        float4 cv, kv;
        cv.x = 1.f - acc[i][0]*inv; cv.y = 1.f - acc[i][1]*inv;
        cv.z = 1.f - acc[i][2]*inv; cv.w = 1.f - acc[i][3]*inv;
        kv.x = expf(-cv.x/0.05f); kv.y = expf(-cv.y/0.05f);
        kv.z = expf(-cv.z/0.05f); kv.w = expf(-cv.w/0.05f);
        size_t base = ((size_t)(b*Nc + n))*Mc + tx*4;
        *(float4*)(g_cost + base) = cv;
        *(float4*)(g_K + base)    = kv;
    }
}

// ---------------- Sinkhorn (plain fp32 — R8 baseline) ----------------
__global__ void __launch_bounds__(512) sinkhorn_kernel() {
    int b   = blockIdx.x;
    int tid = threadIdx.x;
    int lane = tid & 31, wid = tid >> 5;
    __shared__ float sv[Mc];
    __shared__ float snu[Mc];
    __shared__ float sS[16][33];
    __shared__ float sErr[16];
    if (tid < Mc) { sv[tid] = 0.f; snu[tid] = g_nu[b*Mc + tid]; }
    __syncthreads();
    float u[8];
#pragma unroll
    for (int j = 0; j < 8; j++) u[j] = 0.f;
    const float4* Kb = (const float4*)(g_K + (size_t)b*Nc*Mc);
    for (int t = 0; t < ITERS; t++) {
        float vr[Mc];
#pragma unroll
        for (int m = 0; m < Mc; m++) vr[m] = sv[m];
        float S[Mc];
#pragma unroll
        for (int m = 0; m < Mc; m++) S[m] = 0.f;
        float errLoc = 0.f;
#pragma unroll
        for (int j = 0; j < 8; j++) {
            int n = j*512 + tid;
            const float4* kp = Kb + (size_t)n*8;
            float d = 0.f;
#pragma unroll
            for (int q = 0; q < 8; q++) {
                float4 v4 = kp[q];
                d = fmaf(v4.x, vr[q*4+0], d);
                d = fmaf(v4.y, vr[q*4+1], d);
                d = fmaf(v4.z, vr[q*4+2], d);
                d = fmaf(v4.w, vr[q*4+3], d);
            }
            float un = MU_ / (d + 1e-8f);
            errLoc += fabsf(un - u[j]);
            u[j] = un;
#pragma unroll
            for (int q = 0; q < 8; q++) {
                float4 v4 = kp[q];
                S[q*4+0] = fmaf(v4.x, un, S[q*4+0]);
                S[q*4+1] = fmaf(v4.y, un, S[q*4+1]);
                S[q*4+2] = fmaf(v4.z, un, S[q*4+2]);
                S[q*4+3] = fmaf(v4.w, un, S[q*4+3]);
            }
        }
#pragma unroll
        for (int m = 0; m < Mc; m++) S[m] = wsum(S[m]);
        errLoc = wsum(errLoc);
        if (lane == 0) {
#pragma unroll
            for (int m = 0; m < Mc; m++) sS[wid][m] = S[m];
            sErr[wid] = errLoc;
        }
        __syncthreads();
        if (tid < Mc) {
            float s = 0.f;
#pragma unroll
            for (int w = 0; w < 16; w++) s += sS[w][tid];
            float vnew = snu[tid] / (s + 1e-8f);
            sv[tid] = vnew;
            g_vhist[((size_t)b*ITERS + t)*Mc + tid] = vnew;
        }
        if (tid == 32) {
            float e = 0.f;
            for (int w = 0; w < 16; w++) e += sErr[w];
            g_errhist[b*ITERS + t] = e;
        }
        __syncthreads();
    }
}

// ---------------- pick iteration T ----------------
__global__ void pick_kernel() {
    __shared__ int sT;
    if (threadIdx.x == 0) {
        int T = ITERS - 1;
        for (int t = 0; t < ITERS; t++) {
            float e = 0.f;
            for (int b = 0; b < Bc; b++) e += g_errhist[b*ITERS + t];
            e *= (1.0f/(float)Bc);
            if (e < 0.1f) { T = t; break; }
        }
        sT = T;
    }
    __syncthreads();
    int T = sT;
    int m = threadIdx.x;
    if (m < Mc) {
        for (int b = 0; b < Bc; b++) {
            g_vfin[b*Mc + m]  = g_vhist[((size_t)b*ITERS + T)*Mc + m];
            g_vprev[b*Mc + m] = (T > 0) ? g_vhist[((size_t)b*ITERS + T - 1)*Mc + m] : 0.f;
        }
    }
}

// ---------------- finalize: pi, ot partials, pi_norm ----------------
__global__ void __launch_bounds__(256) finalize_kernel(float* __restrict__ out) {
    int b  = blockIdx.x >> 3;
    int r0 = (blockIdx.x & 7) * 512;
    __shared__ float svp[Mc], svf[Mc];
    __shared__ float red[256];
    int tid = threadIdx.x;
    if (tid < Mc) { svp[tid] = g_vprev[b*Mc + tid]; svf[tid] = g_vfin[b*Mc + tid]; }
    __syncthreads();
    float vp[Mc], vf[Mc];
#pragma unroll
    for (int m = 0; m < Mc; m++) { vp[m] = svp[m]; vf[m] = svf[m]; }
    float otLoc = 0.f;
    for (int jj = 0; jj < 2; jj++) {
        int n = r0 + jj*256 + tid;
        size_t base = ((size_t)(b*Nc + n))*Mc;
        const float4* kp = (const float4*)(g_K + base);
        const float4* cp = (const float4*)(g_cost + base);
        float kr[Mc];
#pragma unroll
        for (int q = 0; q < 8; q++) {
            float4 v = kp[q];
            kr[q*4+0] = v.x; kr[q*4+1] = v.y; kr[q*4+2] = v.z; kr[q*4+3] = v.w;
        }
        float d = 0.f;
#pragma unroll
        for (int m = 0; m < Mc; m++) d = fmaf(kr[m], vp[m], d);
        float u = MU_ / (d + 1e-8f);
        float pi[Mc]; float s = 0.f;
#pragma unroll
        for (int m = 0; m < Mc; m++) { pi[m] = u * kr[m] * vf[m]; s += pi[m]; }
#pragma unroll
        for (int q = 0; q < 8; q++) {
            float4 c4 = cp[q];
            otLoc += pi[q*4+0]*c4.x + pi[q*4+1]*c4.y + pi[q*4+2]*c4.z + pi[q*4+3]*c4.w;
        }
        float inv = 1.f/(s + 1e-8f);
        float* piOut = out + OUT0 + Bc + base;
#pragma unroll
        for (int q = 0; q < 8; q++) {
            float4 o;  o.x = pi[q*4+0]; o.y = pi[q*4+1]; o.z = pi[q*4+2]; o.w = pi[q*4+3];
            *(float4*)(piOut + q*4) = o;
            float4 pn; pn.x = o.x*inv; pn.y = o.y*inv; pn.z = o.z*inv; pn.w = o.w*inv;
            *(float4*)(g_pn + base + q*4) = pn;
        }
    }
    red[tid] = otLoc;
    __syncthreads();
    for (int s2 = 128; s2 > 0; s2 >>= 1) {
        if (tid < s2) red[tid] += red[tid + s2];
        __syncthreads();
    }
    if (tid == 0) g_otPart[blockIdx.x] = red[0];
}

__global__ void otsum_kernel(float* __restrict__ out) {
    int b = threadIdx.x;
    if (b < Bc) {
        float s = 0.f;
        for (int i = 0; i < 8; i++) s += g_otPart[b*8 + i];
        out[OUT0 + b] = s;
    }
}

// ---------------- split-bf16 tensor-core GEMM: H = A'h/l @ B'h/l + bias ----------------
// 128x128 tile, BK=32, 8 warps (4m x 2n), each warp 32x64 via m16n8k16.
#define SPAD 40
__global__ void __launch_bounds__(256) gemm_tc_kernel(const float* __restrict__ bias) {
    __shared__ __nv_bfloat16 sAh[128*SPAD], sAl[128*SPAD];
    __shared__ __nv_bfloat16 sBh[128*SPAD], sBl[128*SPAD];
    int row0 = blockIdx.x * 128;
    int c0   = blockIdx.y * 128;
    int b    = row0 >> 12;
    int tid  = threadIdx.x, lane = tid & 31, w = tid >> 5;
    int wm = (w >> 1) * 32, wn = (w & 1) * 64;

    const __nv_bfloat16* pBh = g_Bth + (size_t)b*Cc*KK;
    const __nv_bfloat16* pBl = g_Btl + (size_t)b*Cc*KK;

    float acc[2][8][4];
#pragma unroll
    for (int mi = 0; mi < 2; mi++)
#pragma unroll
        for (int nf = 0; nf < 8; nf++)
#pragma unroll
            for (int q = 0; q < 4; q++) acc[mi][nf][q] = 0.f;

    // ldmatrix lane addressing (within a 16x16 A tile / 16x16 B group)
    int a_r = (lane & 7) + ((lane >> 3) & 1) * 8;
    int a_c2 = (lane >> 4) * 8;                 // + ks
    int b_r = (lane & 7) + (lane >> 4) * 8;
    int b_c2 = ((lane >> 3) & 1) * 8;           // + ks

    for (int kt = 0; kt < 17; kt++) {
        int k0 = kt * 32;
        __syncthreads();
#pragma unroll
        for (int q = 0; q < 2; q++) {
            int id = tid*2 + q;
            int r = id >> 2, kq = id & 3;
            size_t ga = (size_t)(row0 + r)*KK + k0 + kq*8;
            *(uint4*)(sAh + r*SPAD + kq*8) = *(const uint4*)(g_Ah + ga);
            *(uint4*)(sAl + r*SPAD + kq*8) = *(const uint4*)(g_Al + ga);
            size_t gb = (size_t)(c0 + r)*KK + k0 + kq*8;
            *(uint4*)(sBh + r*SPAD + kq*8) = *(const uint4*)(pBh + gb);
            *(uint4*)(sBl + r*SPAD + kq*8) = *(const uint4*)(pBl + gb);
        }
        __syncthreads();
#pragma unroll
        for (int ks = 0; ks < 32; ks += 16) {
            unsigned ah[2][4], al[2][4];
#pragma unroll
            for (int mi = 0; mi < 2; mi++) {
                uint32_t adh = (uint32_t)__cvta_generic_to_shared(
                    sAh + (wm + mi*16 + a_r)*SPAD + ks + a_c2);
                ldsm_x4(ah[mi], adh);
                uint32_t adl = (uint32_t)__cvta_generic_to_shared(
                    sAl + (wm + mi*16 + a_r)*SPAD + ks + a_c2);
                ldsm_x4(al[mi], adl);
            }
#pragma unroll
            for (int nj = 0; nj < 4; nj++) {
                unsigned bh4[4], bl4[4];
                uint32_t bdh = (uint32_t)__cvta_generic_to_shared(
                    sBh + (wn + nj*16 + b_r)*SPAD + ks + b_c2);
                ldsm_x4(bh4, bdh);
                uint32_t bdl = (uint32_t)__cvta_generic_to_shared(
                    sBl + (wn + nj*16 + b_r)*SPAD + ks + b_c2);
                ldsm_x4(bl4, bdl);
#pragma unroll
                for (int h = 0; h < 2; h++) {
                    int nf = nj*2 + h;
#pragma unroll
                    for (int mi = 0; mi < 2; mi++) {
                        mma_bf16(acc[mi][nf], ah[mi], bh4 + 2*h);
                        mma_bf16(acc[mi][nf], ah[mi], bl4 + 2*h);
                        mma_bf16(acc[mi][nf], al[mi], bh4 + 2*h);
                    }
                }
            }
        }
    }

    // epilogue: bias add + store to g_H
#pragma unroll
    for (int mi = 0; mi < 2; mi++) {
#pragma unroll
        for (int nf = 0; nf < 8; nf++) {
            int rowa = row0 + wm + mi*16 + (lane >> 2);
            int col  = c0 + wn + nf*8 + (lane & 3)*2;
            float2 bv = *(const float2*)(bias + col);
            float2 o0; o0.x = acc[mi][nf][0] + bv.x; o0.y = acc[mi][nf][1] + bv.y;
            *(float2*)(g_H + (size_t)rowa*Cc + col) = o0;
            float2 o1; o1.x = acc[mi][nf][2] + bv.x; o1.y = acc[mi][nf][3] + bv.y;
            *(float2*)(g_H + (size_t)(rowa + 8)*Cc + col) = o1;
        }
    }
}

// ---------------- LayerNorm ----------------
__global__ void __launch_bounds__(256) ln_kernel(float* __restrict__ out,
                                                 const float* __restrict__ gamma,
                                                 const float* __restrict__ beta) {
    int row  = blockIdx.x*8 + (threadIdx.x >> 5);
    int lane = threadIdx.x & 31;
    const float* h = g_H + (size_t)row*Cc;
    float4 x[4];
    float s = 0.f;
#pragma unroll
    for (int q = 0; q < 4; q++) {
        x[q] = *(const float4*)(h + q*128 + lane*4);
        s += x[q].x + x[q].y + x[q].z + x[q].w;
    }
    s = wsum(s);
    float mean = s * (1.0f/512.0f);
    float var = 0.f;
#pragma unroll
    for (int q = 0; q < 4; q++) {
        float a = x[q].x - mean, b2 = x[q].y - mean, c = x[q].z - mean, d = x[q].w - mean;
        var += a*a + b2*b2 + c*c + d*d;
    }
    var = wsum(var) * (1.0f/512.0f);
    float inv = rsqrtf(var + 1e-5f);
    float* o = out + (size_t)row*Cc;
#pragma unroll
    for (int q = 0; q < 4; q++) {
        int c = q*128 + lane*4;
        float4 g4 = *(const float4*)(gamma + c);
        float4 b4 = *(const float4*)(beta + c);
        float4 r;
        r.x = (x[q].x - mean)*inv*g4.x + b4.x;
        r.y = (x[q].y - mean)*inv*g4.y + b4.y;
        r.z = (x[q].z - mean)*inv*g4.z + b4.z;
        r.w = (x[q].w - mean)*inv*g4.w + b4.w;
        *(float4*)(o + c) = r;
    }
}

// ---------------- launcher ----------------
extern "C" void kernel_launch(void* const* d_in, const int* in_sizes, int n_in,
                              void* d_out, int out_size) {
    const float* src   = (const float*)d_in[0];
    const float* tgt   = (const float*)d_in[1];
    const float* score = (const float*)d_in[2];
    const float* W     = (const float*)d_in[3];
    const float* bias  = (const float*)d_in[4];
    const float* gamma = (const float*)d_in[5];
    const float* beta  = (const float*)d_in[6];
    float* out = (float*)d_out;

    reset_kernel<<<1, 512>>>();
    hist_kernel<<<Bc*16, 256>>>(score);
    nu_kernel<<<1, 512>>>();
    yn_kernel<<<Bc, 512>>>(tgt);
    yt_kernel<<<Bc*4, 128>>>(tgt, W);
    convB_kernel<<<dim3(17, 16, Bc), dim3(32, 8)>>>(W);
    convA_src_kernel<<<32768, 256>>>(src);
    cost_kernel<<<Bc*32, 256>>>(src);
    sinkhorn_kernel<<<Bc, 512>>>();
    pick_kernel<<<1, 32>>>();
    finalize_kernel<<<Bc*8, 256>>>(out);
    convA_pn_kernel<<<2048, 256>>>();
    otsum_kernel<<<1, 32>>>(out);
    gemm_tc_kernel<<<dim3(512, 4), 256>>>(bias);
    ln_kernel<<<8192, 256>>>(out, gamma, beta);
}

// round 13
// speedup vs baseline: 1.3930x; 1.1078x over previous
#include <cuda_runtime.h>
#include <cuda_bf16.h>
#include <cstdint>
#include <cstddef>

#define Bc 16
#define Nc 4096
#define Cc 512
#define Mc 32
#define ITERS 50
#define MU_ (1.0f/4096.0f)
#define OUT0 ((size_t)Bc*Nc*Cc)
#define KK 544                 // 512 + 32 fused-K
#define ROWS ((size_t)Bc*Nc)   // 65536
#define SPAD 40
#define GEMM_SMEM (8*128*SPAD*sizeof(__nv_bfloat16))   // 4 arrays x 2 stages = 81920 B

// ---------------- device scratch ----------------
static __device__ float g_yn[Bc*Mc*Cc];
static __device__ float g_Yt[Bc*Mc*Cc];
static __device__ float g_cost[(size_t)Bc*Nc*Mc];
static __device__ float g_K[(size_t)Bc*Nc*Mc];
static __device__ float g_nu[Bc*Mc];
static __device__ int   g_counts[Bc*Mc];
static __device__ float g_vhist[Bc*ITERS*Mc];
static __device__ float g_errhist[Bc*ITERS];
static __device__ float g_vfin[Bc*Mc];
static __device__ float g_vprev[Bc*Mc];
static __device__ float g_pn[(size_t)Bc*Nc*Mc];
static __device__ float g_otPart[Bc*8];
static __device__ float g_H[(size_t)Bc*Nc*Cc];
static __device__ __nv_bfloat16 g_Ah[ROWS*KK];
static __device__ __nv_bfloat16 g_Al[ROWS*KK];
static __device__ __nv_bfloat16 g_Bth[(size_t)Bc*Cc*KK];
static __device__ __nv_bfloat16 g_Btl[(size_t)Bc*Cc*KK];

__device__ __forceinline__ float wsum(float v) {
    v += __shfl_xor_sync(0xffffffffu, v, 16);
    v += __shfl_xor_sync(0xffffffffu, v, 8);
    v += __shfl_xor_sync(0xffffffffu, v, 4);
    v += __shfl_xor_sync(0xffffffffu, v, 2);
    v += __shfl_xor_sync(0xffffffffu, v, 1);
    return v;
}

__device__ __forceinline__ void split_bf16(float x, __nv_bfloat16& h, __nv_bfloat16& l) {
    h = __float2bfloat16(x);
    l = __float2bfloat16(x - __bfloat162float(h));
}

__device__ __forceinline__ void ldsm_x4(unsigned* r, uint32_t addr) {
    asm volatile("ldmatrix.sync.aligned.m8n8.x4.shared.b16 {%0,%1,%2,%3}, [%4];\n"
        : "=r"(r[0]), "=r"(r[1]), "=r"(r[2]), "=r"(r[3]) : "r"(addr));
}

__device__ __forceinline__ void mma_bf16(float* d, const unsigned* a, const unsigned* b) {
    asm volatile("mma.sync.aligned.m16n8k16.row.col.f32.bf16.bf16.f32 "
        "{%0,%1,%2,%3}, {%4,%5,%6,%7}, {%8,%9}, {%0,%1,%2,%3};\n"
        : "+f"(d[0]), "+f"(d[1]), "+f"(d[2]), "+f"(d[3])
        : "r"(a[0]), "r"(a[1]), "r"(a[2]), "r"(a[3]), "r"(b[0]), "r"(b[1]));
}

__device__ __forceinline__ void cpa16(uint32_t s, const void* g) {
    asm volatile("cp.async.cg.shared.global [%0], [%1], 16;\n" :: "r"(s), "l"(g));
}
__device__ __forceinline__ void cp_commit() {
    asm volatile("cp.async.commit_group;\n");
}

// ---------------- reset ----------------
__global__ void reset_kernel() {
    int tid = threadIdx.x;
    if (tid < Bc*Mc) g_counts[tid] = 0;
}

// ---------------- nu histogram ----------------
__global__ void hist_kernel(const float* __restrict__ score) {
    __shared__ int h[Mc];
    int b = blockIdx.x >> 4, chunk = blockIdx.x & 15;
    int tid = threadIdx.x;
    if (tid < Mc) h[tid] = 0;
    __syncthreads();
    int p = chunk*256 + tid;
    const float* s = score + (size_t)b*Mc*Nc + p;
    float best = s[0]; int bi = 0;
#pragma unroll
    for (int k = 1; k < Mc; k++) {
        float v = s[(size_t)k*Nc];
        if (v > best) { best = v; bi = k; }
    }
    atomicAdd(&h[bi], 1);
    __syncthreads();
    if (tid < Mc) atomicAdd(&g_counts[b*Mc + tid], h[tid]);
}

__global__ void nu_kernel() {
    int tid = threadIdx.x;
    int b = tid >> 5, m = tid & 31;
    float c = (float)g_counts[b*Mc + m];
    float total = wsum(c);
    float nu1 = c / (total + 1e-8f);
    float nu2 = nu1 + 1e-6f;
    float s2 = wsum(nu2);
    g_nu[b*Mc + m] = nu2 / s2;
}

// ---------------- target row-normalize ----------------
__global__ void yn_kernel(const float* __restrict__ tgt) {
    int b = blockIdx.x;
    int w = threadIdx.x >> 5, lane = threadIdx.x & 31;
    for (int m = w; m < Mc; m += 16) {
        const float* y = tgt + ((size_t)(b*Mc + m))*Cc;
        float ss = 0.f;
        for (int j = lane*4; j < Cc; j += 128) {
            float4 v = *(const float4*)(y + j);
            ss += v.x*v.x + v.y*v.y + v.z*v.z + v.w*v.w;
        }
        ss = wsum(ss);
        float inv = rsqrtf(ss);
        for (int j = lane*4; j < Cc; j += 128) {
            float4 v = *(const float4*)(y + j);
            float4 o; o.x = v.x*inv; o.y = v.y*inv; o.z = v.z*inv; o.w = v.w*inv;
            *(float4*)(g_yn + ((size_t)(b*Mc + m))*Cc + j) = o;
        }
    }
}

// ---------------- Yt = target @ W_bot ----------------
__global__ void __launch_bounds__(128) yt_kernel(const float* __restrict__ tgt,
                                                 const float* __restrict__ W) {
    int b  = blockIdx.x >> 2;
    int c0 = (blockIdx.x & 3) * 128;
    int c  = c0 + threadIdx.x;
    __shared__ float st[64][33];
    float acc[Mc];
#pragma unroll
    for (int m = 0; m < Mc; m++) acc[m] = 0.f;
    for (int k0 = 0; k0 < Cc; k0 += 64) {
        __syncthreads();
        for (int i = threadIdx.x; i < 512; i += 128) {
            int m = i >> 4, kq = i & 15;
            float4 v = *(const float4*)(tgt + ((size_t)(b*Mc + m))*Cc + k0 + kq*4);
            st[kq*4+0][m] = v.x; st[kq*4+1][m] = v.y;
            st[kq*4+2][m] = v.z; st[kq*4+3][m] = v.w;
        }
        __syncthreads();
        for (int kk = 0; kk < 64; kk++) {
            float w = W[(size_t)(Cc + k0 + kk)*Cc + c];
#pragma unroll
            for (int m = 0; m < Mc; m++) acc[m] = fmaf(st[kk][m], w, acc[m]);
        }
    }
#pragma unroll
    for (int m = 0; m < Mc; m++)
        g_Yt[((size_t)(b*Mc + m))*Cc + c] = acc[m];
}

// ---------------- convB: transposed split-bf16 B' = [W_top ; Yt_b], layout [b][c][k] ----------------
__global__ void convB_kernel(const float* __restrict__ W) {
    __shared__ float t[32][33];
    int kt = blockIdx.x, ct = blockIdx.y, b = blockIdx.z;
    int tx = threadIdx.x, ty = threadIdx.y;
#pragma unroll
    for (int i = 0; i < 4; i++) {
        int k = kt*32 + ty + i*8;
        int c = ct*32 + tx;
        float v = (k < Cc) ? W[(size_t)k*Cc + c]
                           : g_Yt[((size_t)(b*Mc + (k - Cc)))*Cc + c];
        t[ty + i*8][tx] = v;
    }
    __syncthreads();
#pragma unroll
    for (int i = 0; i < 4; i++) {
        int c = ct*32 + ty + i*8;
        int k = kt*32 + tx;
        float v = t[tx][ty + i*8];
        __nv_bfloat16 h, l; split_bf16(v, h, l);
        size_t o = (size_t)b*Cc*KK + (size_t)c*KK + k;
        g_Bth[o] = h; g_Btl[o] = l;
    }
}

// ---------------- convA: split-bf16 of A' src part ----------------
__global__ void __launch_bounds__(256) convA_src_kernel(const float* __restrict__ src) {
    size_t gid = (size_t)blockIdx.x*256 + threadIdx.x;
    size_t row = gid >> 7; int kq = (int)(gid & 127);
    float4 v = *(const float4*)(src + row*Cc + kq*4);
    __nv_bfloat16 h[4], l[4];
    split_bf16(v.x, h[0], l[0]); split_bf16(v.y, h[1], l[1]);
    split_bf16(v.z, h[2], l[2]); split_bf16(v.w, h[3], l[3]);
    size_t o = row*KK + kq*4;
    *(__nv_bfloat162*)(g_Ah + o)     = __nv_bfloat162{h[0], h[1]};
    *(__nv_bfloat162*)(g_Ah + o + 2) = __nv_bfloat162{h[2], h[3]};
    *(__nv_bfloat162*)(g_Al + o)     = __nv_bfloat162{l[0], l[1]};
    *(__nv_bfloat162*)(g_Al + o + 2) = __nv_bfloat162{l[2], l[3]};
}

// ---------------- cost & K ----------------
__global__ void __launch_bounds__(256) cost_kernel(const float* __restrict__ src) {
    __shared__ float As[32][132];
    __shared__ float Bs[32][36];
    int b  = blockIdx.x >> 5;
    int r0 = (blockIdx.x & 31) * 128;
    int tid = threadIdx.x;
    int tx = tid & 7, ty = tid >> 3;
    float acc[4][4], accn[4];
#pragma unroll
    for (int i = 0; i < 4; i++) {
        accn[i] = 0.f;
#pragma unroll
        for (int j = 0; j < 4; j++) acc[i][j] = 0.f;
    }
    for (int k0 = 0; k0 < Cc; k0 += 32) {
        __syncthreads();
        for (int i = tid; i < 1024; i += 256) {
            int r = i >> 3, kq = i & 7;
            float4 v = *(const float4*)(src + ((size_t)(b*Nc + r0 + r))*Cc + k0 + kq*4);
            As[kq*4+0][r] = v.x; As[kq*4+1][r] = v.y;
            As[kq*4+2][r] = v.z; As[kq*4+3][r] = v.w;
        }
        if (tid < 256) {
            int m = tid >> 3, kq = tid & 7;
            float4 v = *(const float4*)(g_yn + ((size_t)(b*Mc + m))*Cc + k0 + kq*4);
            Bs[kq*4+0][m] = v.x; Bs[kq*4+1][m] = v.y;
            Bs[kq*4+2][m] = v.z; Bs[kq*4+3][m] = v.w;
        }
        __syncthreads();
#pragma unroll
        for (int k = 0; k < 32; k++) {
            float a[4], bb[4];
#pragma unroll
            for (int i = 0; i < 4; i++) a[i] = As[k][ty*4 + i];
#pragma unroll
            for (int j = 0; j < 4; j++) bb[j] = Bs[k][tx*4 + j];
#pragma unroll
            for (int i = 0; i < 4; i++) {
                accn[i] = fmaf(a[i], a[i], accn[i]);
#pragma unroll
                for (int j = 0; j < 4; j++) acc[i][j] = fmaf(a[i], bb[j], acc[i][j]);
            }
        }
    }
#pragma unroll
    for (int i = 0; i < 4; i++) {
        int n = r0 + ty*4 + i;
        float inv = rsqrtf(accn[i]);
        float4 cv, kv;
        cv.x = 1.f - acc[i][0]*inv; cv.y = 1.f - acc[i][1]*inv;
        cv.z = 1.f - acc[i][2]*inv; cv.w = 1.f - acc[i][3]*inv;
        kv.x = expf(-cv.x/0.05f); kv.y = expf(-cv.y/0.05f);
        kv.z = expf(-cv.z/0.05f); kv.w = expf(-cv.w/0.05f);
        size_t base = ((size_t)(b*Nc + n))*Mc + tx*4;
        *(float4*)(g_cost + base) = cv;
        *(float4*)(g_K + base)    = kv;
    }
}

// ---------------- Sinkhorn: one CTA per batch, K row staged once in registers ----------------
__global__ void __launch_bounds__(512) sinkhorn_kernel() {
    int b   = blockIdx.x;
    int tid = threadIdx.x;
    int lane = tid & 31, wid = tid >> 5;
    __shared__ float sv[Mc];
    __shared__ float snu[Mc];
    __shared__ float sS[16][33];
    __shared__ float sErr[16];
    if (tid < Mc) { sv[tid] = 0.f; snu[tid] = g_nu[b*Mc + tid]; }
    __syncthreads();
    float u[8];
#pragma unroll
    for (int j = 0; j < 8; j++) u[j] = 0.f;
    const float4* Kb = (const float4*)(g_K + (size_t)b*Nc*Mc);
    for (int t = 0; t < ITERS; t++) {
        float vr[Mc];
#pragma unroll
        for (int m = 0; m < Mc; m++) vr[m] = sv[m];
        float S[Mc];
#pragma unroll
        for (int m = 0; m < Mc; m++) S[m] = 0.f;
        float errLoc = 0.f;
#pragma unroll
        for (int j = 0; j < 8; j++) {
            int n = j*512 + tid;
            const float4* kp = Kb + (size_t)n*8;
            float kr[Mc];
#pragma unroll
            for (int q = 0; q < 8; q++) {
                float4 v4 = kp[q];
                kr[q*4+0] = v4.x; kr[q*4+1] = v4.y;
                kr[q*4+2] = v4.z; kr[q*4+3] = v4.w;
            }
            float d = 0.f;
#pragma unroll
            for (int m = 0; m < Mc; m++) d = fmaf(kr[m], vr[m], d);
            float un = MU_ / (d + 1e-8f);
            errLoc += fabsf(un - u[j]);
            u[j] = un;
#pragma unroll
            for (int m = 0; m < Mc; m++) S[m] = fmaf(kr[m], un, S[m]);
        }
#pragma unroll
        for (int m = 0; m < Mc; m++) S[m] = wsum(S[m]);
        errLoc = wsum(errLoc);
        if (lane == 0) {
#pragma unroll
            for (int m = 0; m < Mc; m++) sS[wid][m] = S[m];
            sErr[wid] = errLoc;
        }
        __syncthreads();
        if (tid < Mc) {
            float s = 0.f;
#pragma unroll
            for (int w = 0; w < 16; w++) s += sS[w][tid];
            float vnew = snu[tid] / (s + 1e-8f);
            sv[tid] = vnew;
            g_vhist[((size_t)b*ITERS + t)*Mc + tid] = vnew;
        }
        if (tid == 32) {
            float e = 0.f;
            for (int w = 0; w < 16; w++) e += sErr[w];
            g_errhist[b*ITERS + t] = e;
        }
        __syncthreads();
    }
}

// ---------------- pick iteration T ----------------
__global__ void pick_kernel() {
    __shared__ int sT;
    if (threadIdx.x == 0) {
        int T = ITERS - 1;
        for (int t = 0; t < ITERS; t++) {
            float e = 0.f;
            for (int b = 0; b < Bc; b++) e += g_errhist[b*ITERS + t];
            e *= (1.0f/(float)Bc);
            if (e < 0.1f) { T = t; break; }
        }
        sT = T;
    }
    __syncthreads();
    int T = sT;
    int m = threadIdx.x;
    if (m < Mc) {
        for (int b = 0; b < Bc; b++) {
            g_vfin[b*Mc + m]  = g_vhist[((size_t)b*ITERS + T)*Mc + m];
            g_vprev[b*Mc + m] = (T > 0) ? g_vhist[((size_t)b*ITERS + T - 1)*Mc + m] : 0.f;
        }
    }
}

// ---------------- finalize: pi, ot partials, pi_norm + fused bf16 split of pn ----------------
__global__ void __launch_bounds__(256) finalize_kernel(float* __restrict__ out) {
    int b  = blockIdx.x >> 3;
    int r0 = (blockIdx.x & 7) * 512;
    __shared__ float svp[Mc], svf[Mc];
    __shared__ float red[256];
    int tid = threadIdx.x;
    if (tid < Mc) { svp[tid] = g_vprev[b*Mc + tid]; svf[tid] = g_vfin[b*Mc + tid]; }
    __syncthreads();
    float vp[Mc], vf[Mc];
#pragma unroll
    for (int m = 0; m < Mc; m++) { vp[m] = svp[m]; vf[m] = svf[m]; }
    float otLoc = 0.f;
    for (int jj = 0; jj < 2; jj++) {
        int n = r0 + jj*256 + tid;
        size_t base = ((size_t)(b*Nc + n))*Mc;
        const float4* kp = (const float4*)(g_K + base);
        const float4* cp = (const float4*)(g_cost + base);
        float kr[Mc];
#pragma unroll
        for (int q = 0; q < 8; q++) {
            float4 v = kp[q];
            kr[q*4+0] = v.x; kr[q*4+1] = v.y; kr[q*4+2] = v.z; kr[q*4+3] = v.w;
        }
        float d = 0.f;
#pragma unroll
        for (int m = 0; m < Mc; m++) d = fmaf(kr[m], vp[m], d);
        float u = MU_ / (d + 1e-8f);
        float pi[Mc]; float s = 0.f;
#pragma unroll
        for (int m = 0; m < Mc; m++) { pi[m] = u * kr[m] * vf[m]; s += pi[m]; }
#pragma unroll
        for (int q = 0; q < 8; q++) {
            float4 c4 = cp[q];
            otLoc += pi[q*4+0]*c4.x + pi[q*4+1]*c4.y + pi[q*4+2]*c4.z + pi[q*4+3]*c4.w;
        }
        float inv = 1.f/(s + 1e-8f);
        float* piOut = out + OUT0 + Bc + base;
        size_t arow = ((size_t)(b*Nc + n))*KK + Cc;
#pragma unroll
        for (int q = 0; q < 8; q++) {
            float4 o;  o.x = pi[q*4+0]; o.y = pi[q*4+1]; o.z = pi[q*4+2]; o.w = pi[q*4+3];
            *(float4*)(piOut + q*4) = o;
            float4 pn; pn.x = o.x*inv; pn.y = o.y*inv; pn.z = o.z*inv; pn.w = o.w*inv;
            *(float4*)(g_pn + base + q*4) = pn;
            __nv_bfloat16 h[4], l[4];
            split_bf16(pn.x, h[0], l[0]); split_bf16(pn.y, h[1], l[1]);
            split_bf16(pn.z, h[2], l[2]); split_bf16(pn.w, h[3], l[3]);
            *(__nv_bfloat162*)(g_Ah + arow + q*4)     = __nv_bfloat162{h[0], h[1]};
            *(__nv_bfloat162*)(g_Ah + arow + q*4 + 2) = __nv_bfloat162{h[2], h[3]};
            *(__nv_bfloat162*)(g_Al + arow + q*4)     = __nv_bfloat162{l[0], l[1]};
            *(__nv_bfloat162*)(g_Al + arow + q*4 + 2) = __nv_bfloat162{l[2], l[3]};
        }
    }
    red[tid] = otLoc;
    __syncthreads();
    for (int s2 = 128; s2 > 0; s2 >>= 1) {
        if (tid < s2) red[tid] += red[tid + s2];
        __syncthreads();
    }
    if (tid == 0) g_otPart[blockIdx.x] = red[0];
}

__global__ void otsum_kernel(float* __restrict__ out) {
    int b = threadIdx.x;
    if (b < Bc) {
        float s = 0.f;
        for (int i = 0; i < 8; i++) s += g_otPart[b*8 + i];
        out[OUT0 + b] = s;
    }
}

// ---------------- split-bf16 TC GEMM, 2-stage cp.async pipeline ----------------
__global__ void __launch_bounds__(256) gemm_tc_kernel(const float* __restrict__ bias) {
    extern __shared__ __nv_bfloat16 smem[];
    const int STG = 128*SPAD;           // elems per array per stage
    __nv_bfloat16* sAh = smem;          // [2][STG]
    __nv_bfloat16* sAl = smem + 2*STG;
    __nv_bfloat16* sBh = smem + 4*STG;
    __nv_bfloat16* sBl = smem + 6*STG;

    int row0 = blockIdx.x * 128;
    int c0   = blockIdx.y * 128;
    int b    = row0 >> 12;
    int tid  = threadIdx.x, lane = tid & 31, w = tid >> 5;
    int wm = (w >> 1) * 32, wn = (w & 1) * 64;

    const __nv_bfloat16* pBh = g_Bth + (size_t)b*Cc*KK;
    const __nv_bfloat16* pBl = g_Btl + (size_t)b*Cc*KK;

    // per-thread cp.async indices (2 chunks of 16B per array)
    int id0 = tid*2, id1 = tid*2 + 1;
    int r0a = id0 >> 2, k0a = (id0 & 3) * 8;
    int r1a = id1 >> 2, k1a = (id1 & 3) * 8;

    uint32_t base_sh = (uint32_t)__cvta_generic_to_shared(smem);

    float acc[2][8][4];
#pragma unroll
    for (int mi = 0; mi < 2; mi++)
#pragma unroll
        for (int nf = 0; nf < 8; nf++)
#pragma unroll
            for (int q = 0; q < 4; q++) acc[mi][nf][q] = 0.f;

    int a_r = (lane & 7) + ((lane >> 3) & 1) * 8;
    int a_c2 = (lane >> 4) * 8;
    int b_r = (lane & 7) + (lane >> 4) * 8;
    int b_c2 = ((lane >> 3) & 1) * 8;

    // issue loads for a k-tile into stage st
    auto load_tile = [&](int kt, int st) {
        int k0 = kt * 32;
        uint32_t so = (uint32_t)(st * STG) * 2u;   // byte offset of stage
        {
            size_t ga0 = (size_t)(row0 + r0a)*KK + k0 + k0a;
            size_t ga1 = (size_t)(row0 + r1a)*KK + k0 + k1a;
            uint32_t s0 = base_sh + so + (uint32_t)(r0a*SPAD + k0a)*2u;
            uint32_t s1 = base_sh + so + (uint32_t)(r1a*SPAD + k1a)*2u;
            cpa16(s0, g_Ah + ga0);
            cpa16(s1, g_Ah + ga1);
            cpa16(s0 + 2u*2*STG, g_Al + ga0);
            cpa16(s1 + 2u*2*STG, g_Al + ga1);
            size_t gb0 = (size_t)(c0 + r0a)*KK + k0 + k0a;
            size_t gb1 = (size_t)(c0 + r1a)*KK + k0 + k1a;
            cpa16(s0 + 4u*2*STG, pBh + gb0);
            cpa16(s1 + 4u*2*STG, pBh + gb1);
            cpa16(s0 + 6u*2*STG, pBl + gb0);
            cpa16(s1 + 6u*2*STG, pBl + gb1);
        }
        cp_commit();
    };

    load_tile(0, 0);

#pragma unroll 1
    for (int kt = 0; kt < 17; kt++) {
        int st = kt & 1;
        if (kt + 1 < 17) {
            load_tile(kt + 1, st ^ 1);
            asm volatile("cp.async.wait_group 1;\n");
        } else {
            asm volatile("cp.async.wait_group 0;\n");
        }
        __syncthreads();

        __nv_bfloat16* cAh = sAh + st*STG;
        __nv_bfloat16* cAl = sAl + st*STG;
        __nv_bfloat16* cBh = sBh + st*STG;
        __nv_bfloat16* cBl = sBl + st*STG;
#pragma unroll
        for (int ks = 0; ks < 32; ks += 16) {
            unsigned ah[2][4], al[2][4];
#pragma unroll
            for (int mi = 0; mi < 2; mi++) {
                ldsm_x4(ah[mi], (uint32_t)__cvta_generic_to_shared(
                    cAh + (wm + mi*16 + a_r)*SPAD + ks + a_c2));
                ldsm_x4(al[mi], (uint32_t)__cvta_generic_to_shared(
                    cAl + (wm + mi*16 + a_r)*SPAD + ks + a_c2));
            }
#pragma unroll
            for (int nj = 0; nj < 4; nj++) {
                unsigned bh4[4], bl4[4];
                ldsm_x4(bh4, (uint32_t)__cvta_generic_to_shared(
                    cBh + (wn + nj*16 + b_r)*SPAD + ks + b_c2));
                ldsm_x4(bl4, (uint32_t)__cvta_generic_to_shared(
                    cBl + (wn + nj*16 + b_r)*SPAD + ks + b_c2));
#pragma unroll
                for (int h = 0; h < 2; h++) {
                    int nf = nj*2 + h;
#pragma unroll
                    for (int mi = 0; mi < 2; mi++) {
                        mma_bf16(acc[mi][nf], ah[mi], bh4 + 2*h);
                        mma_bf16(acc[mi][nf], ah[mi], bl4 + 2*h);
                        mma_bf16(acc[mi][nf], al[mi], bh4 + 2*h);
                    }
                }
            }
        }
        __syncthreads();
    }

#pragma unroll
    for (int mi = 0; mi < 2; mi++) {
#pragma unroll
        for (int nf = 0; nf < 8; nf++) {
            int rowa = row0 + wm + mi*16 + (lane >> 2);
            int col  = c0 + wn + nf*8 + (lane & 3)*2;
            float2 bv = *(const float2*)(bias + col);
            float2 o0; o0.x = acc[mi][nf][0] + bv.x; o0.y = acc[mi][nf][1] + bv.y;
            *(float2*)(g_H + (size_t)rowa*Cc + col) = o0;
            float2 o1; o1.x = acc[mi][nf][2] + bv.x; o1.y = acc[mi][nf][3] + bv.y;
            *(float2*)(g_H + (size_t)(rowa + 8)*Cc + col) = o1;
        }
    }
}

// ---------------- LayerNorm ----------------
__global__ void __launch_bounds__(256) ln_kernel(float* __restrict__ out,
                                                 const float* __restrict__ gamma,
                                                 const float* __restrict__ beta) {
    int row  = blockIdx.x*8 + (threadIdx.x >> 5);
    int lane = threadIdx.x & 31;
    const float* h = g_H + (size_t)row*Cc;
    float4 x[4];
    float s = 0.f;
#pragma unroll
    for (int q = 0; q < 4; q++) {
        x[q] = *(const float4*)(h + q*128 + lane*4);
        s += x[q].x + x[q].y + x[q].z + x[q].w;
    }
    s = wsum(s);
    float mean = s * (1.0f/512.0f);
    float var = 0.f;
#pragma unroll
    for (int q = 0; q < 4; q++) {
        float a = x[q].x - mean, b2 = x[q].y - mean, c = x[q].z - mean, d = x[q].w - mean;
        var += a*a + b2*b2 + c*c + d*d;
    }
    var = wsum(var) * (1.0f/512.0f);
    float inv = rsqrtf(var + 1e-5f);
    float* o = out + (size_t)row*Cc;
#pragma unroll
    for (int q = 0; q < 4; q++) {
        int c = q*128 + lane*4;
        float4 g4 = *(const float4*)(gamma + c);
        float4 b4 = *(const float4*)(beta + c);
        float4 r;
        r.x = (x[q].x - mean)*inv*g4.x + b4.x;
        r.y = (x[q].y - mean)*inv*g4.y + b4.y;
        r.z = (x[q].z - mean)*inv*g4.z + b4.z;
        r.w = (x[q].w - mean)*inv*g4.w + b4.w;
        *(float4*)(o + c) = r;
    }
}

// ---------------- launcher ----------------
extern "C" void kernel_launch(void* const* d_in, const int* in_sizes, int n_in,
                              void* d_out, int out_size) {
    const float* src   = (const float*)d_in[0];
    const float* tgt   = (const float*)d_in[1];
    const float* score = (const float*)d_in[2];
    const float* W     = (const float*)d_in[3];
    const float* bias  = (const float*)d_in[4];
    const float* gamma = (const float*)d_in[5];
    const float* beta  = (const float*)d_in[6];
    float* out = (float*)d_out;

    static bool attr_done = false;
    if (!attr_done) {
        cudaFuncSetAttribute(gemm_tc_kernel,
                             cudaFuncAttributeMaxDynamicSharedMemorySize,
                             (int)GEMM_SMEM);
        attr_done = true;
    }

    reset_kernel<<<1, 512>>>();
    hist_kernel<<<Bc*16, 256>>>(score);
    nu_kernel<<<1, 512>>>();
    yn_kernel<<<Bc, 512>>>(tgt);
    yt_kernel<<<Bc*4, 128>>>(tgt, W);
    convB_kernel<<<dim3(17, 16, Bc), dim3(32, 8)>>>(W);
    convA_src_kernel<<<32768, 256>>>(src);
    cost_kernel<<<Bc*32, 256>>>(src);
    sinkhorn_kernel<<<Bc, 512>>>();
    pick_kernel<<<1, 32>>>();
    finalize_kernel<<<Bc*8, 256>>>(out);
    otsum_kernel<<<1, 32>>>(out);
    gemm_tc_kernel<<<dim3(512, 4), 256, GEMM_SMEM>>>(bias);
    ln_kernel<<<8192, 256>>>(out, gamma, beta);
}